// round 3
// baseline (speedup 1.0000x reference)
#include <cuda_runtime.h>

#define N_CELLS 776
#define N_ANCHORS 3
#define N_CH 7
#define CONF_THRESH 0.8f
#define NO_OBJECT 0.5f
#define BLOCK 1024

__global__ __launch_bounds__(BLOCK, 1)
void yolo_loss_kernel(const float* __restrict__ pred,
                      const float* __restrict__ label,
                      float* __restrict__ out)
{
    __shared__ float red[BLOCK];
    __shared__ float lab[N_CH];

    const int tid = threadIdx.x;
    if (tid < N_CH) lab[tid] = label[tid];
    __syncthreads();

    const float lx = lab[0], ly = lab[1], lw = lab[2], lh = lab[3];
    const float lconf = lab[4], lc5 = lab[5], lc6 = lab[6];
    const float area_b = fabsf(lw * lh);
    const float lxm = lx - lw * 0.5f, lym = ly - lh * 0.5f;
    const float lxp = lx + lw * 0.5f, lyp = ly + lh * 0.5f;

    float loss = 0.0f;
    if (tid < N_CELLS) {
        const float* row = pred + (size_t)tid * (N_ANCHORS * N_CH);

        // argmax of IoU over anchors (first-max tie-break)
        float best_iou = -1.0f;
        int best_a = 0;
        #pragma unroll
        for (int a = 0; a < N_ANCHORS; a++) {
            const float px = row[a * N_CH + 0];
            const float py = row[a * N_CH + 1];
            const float pw = row[a * N_CH + 2];
            const float ph = row[a * N_CH + 3];
            const float ax = fmaxf(px - pw * 0.5f, lxm);
            const float ay = fmaxf(py - ph * 0.5f, lym);
            const float bx = fminf(px + pw * 0.5f, lxp);
            const float by = fminf(py + ph * 0.5f, lyp);
            const float inter = fabsf(fmaxf(bx - ax, 0.0f) * fmaxf(by - ay, 0.0f));
            const float area_a = fabsf(pw * ph);
            const float iou = inter / (area_a + area_b - inter);
            if (iou > best_iou) { best_iou = iou; best_a = a; }
        }

        const float* b = row + best_a * N_CH;
        const float b0 = b[0], b1 = b[1];
        const float b4 = b[4], b5 = b[5], b6 = b[6];

        const float dx = lx - b0, dy = ly - b1;
        const float xy_loss = dx * dx + dy * dy;
        const float sdx = sqrtf(lx) - sqrtf(b0);
        const float sdy = sqrtf(ly) - sqrtf(b1);
        const float wh_loss = sdx * sdx + sdy * sdy;

        const bool has_obj = b4 > CONF_THRESH;
        float class_loss = 0.0f;
        if (has_obj) {
            const float d5 = lc5 - b5, d6 = lc6 - b6;
            class_loss = d5 * d5 + d6 * d6;
        }
        const float dc = lconf - b4;
        const float conf_sq = dc * dc;
        const float conf_loss = has_obj ? conf_sq : NO_OBJECT * conf_sq;

        loss = xy_loss + wh_loss + class_loss + conf_loss;
    }

    red[tid] = loss;
    __syncthreads();

    // deterministic tree reduction
    #pragma unroll
    for (int s = BLOCK / 2; s >= 32; s >>= 1) {
        if (tid < s) red[tid] += red[tid + s];
        __syncthreads();
    }
    if (tid < 32) {
        float v = red[tid];
        #pragma unroll
        for (int off = 16; off > 0; off >>= 1)
            v += __shfl_down_sync(0xFFFFFFFF, v, off);
        if (tid == 0) out[0] = v;
    }
}

extern "C" void kernel_launch(void* const* d_in, const int* in_sizes, int n_in,
                              void* d_out, int out_size)
{
    const float* pred  = (const float*)d_in[0];
    const float* label = (const float*)d_in[1];
    float* out = (float*)d_out;
    yolo_loss_kernel<<<1, BLOCK>>>(pred, label, out);
}

// round 7
// speedup vs baseline: 1.0097x; 1.0097x over previous
#include <cuda_runtime.h>

#define N_CELLS 776
#define N_ANCHORS 3
#define N_CH 7
#define CONF_THRESH 0.8f
#define NO_OBJECT 0.5f

#define NB 8      // 8 blocks: 776 = 8 * 97
#define NT 128    // 4 warps per block
#define CPB 97    // cells per block

__device__ float g_partials[NB];
__device__ unsigned int g_ticket = 0;   // reset by last block each launch

__global__ __launch_bounds__(NT, 1)
void yolo_loss_kernel(const float* __restrict__ pred,
                      const float* __restrict__ label,
                      float* __restrict__ out)
{
    __shared__ float warp_sums[NT / 32];
    __shared__ bool is_last;

    const int tid = threadIdx.x;
    const int bid = blockIdx.x;

    // label broadcast loads (uniform address -> single L2/L1 transaction per word)
    const float lx = __ldg(&label[0]);
    const float ly = __ldg(&label[1]);
    const float lw = __ldg(&label[2]);
    const float lh = __ldg(&label[3]);
    const float lconf = __ldg(&label[4]);
    const float lc5 = __ldg(&label[5]);
    const float lc6 = __ldg(&label[6]);

    const float area_b = fabsf(lw * lh);
    const float lxm = lx - lw * 0.5f, lym = ly - lh * 0.5f;
    const float lxp = lx + lw * 0.5f, lyp = ly + lh * 0.5f;
    const float slx = sqrtf(lx), sly = sqrtf(ly);

    float loss = 0.0f;
    const int cell = bid * CPB + tid;
    if (tid < CPB) {
        const float* row = pred + (size_t)cell * (N_ANCHORS * N_CH);

        // argmax of IoU over anchors (first-max tie-break)
        float best_iou = -1.0f;
        int best_a = 0;
        #pragma unroll
        for (int a = 0; a < N_ANCHORS; a++) {
            const float px = row[a * N_CH + 0];
            const float py = row[a * N_CH + 1];
            const float pw = row[a * N_CH + 2];
            const float ph = row[a * N_CH + 3];
            const float ax = fmaxf(px - pw * 0.5f, lxm);
            const float ay = fmaxf(py - ph * 0.5f, lym);
            const float bx = fminf(px + pw * 0.5f, lxp);
            const float by = fminf(py + ph * 0.5f, lyp);
            const float inter = fabsf(fmaxf(bx - ax, 0.0f) * fmaxf(by - ay, 0.0f));
            const float area_a = fabsf(pw * ph);
            const float iou = inter / (area_a + area_b - inter);
            if (iou > best_iou) { best_iou = iou; best_a = a; }
        }

        const float* b = row + best_a * N_CH;
        const float b0 = b[0], b1 = b[1];
        const float b4 = b[4], b5 = b[5], b6 = b[6];

        const float dx = lx - b0, dy = ly - b1;
        const float xy_loss = dx * dx + dy * dy;
        const float sdx = slx - sqrtf(b0);
        const float sdy = sly - sqrtf(b1);
        const float wh_loss = sdx * sdx + sdy * sdy;

        const bool has_obj = b4 > CONF_THRESH;
        float class_loss = 0.0f;
        if (has_obj) {
            const float d5 = lc5 - b5, d6 = lc6 - b6;
            class_loss = d5 * d5 + d6 * d6;
        }
        const float dc = lconf - b4;
        const float conf_sq = dc * dc;
        const float conf_loss = has_obj ? conf_sq : NO_OBJECT * conf_sq;

        loss = xy_loss + wh_loss + class_loss + conf_loss;
    }

    // warp reduction (all 128 threads participate; inactive lanes carry 0)
    #pragma unroll
    for (int off = 16; off > 0; off >>= 1)
        loss += __shfl_down_sync(0xFFFFFFFF, loss, off);
    if ((tid & 31) == 0) warp_sums[tid >> 5] = loss;
    __syncthreads();

    if (tid == 0) {
        float p = warp_sums[0] + warp_sums[1] + warp_sums[2] + warp_sums[3];
        g_partials[bid] = p;
        __threadfence();                       // make partial visible chip-wide
        unsigned int t = atomicAdd(&g_ticket, 1u);
        is_last = (t == NB - 1);
    }
    __syncthreads();

    // last-finishing block combines partials in FIXED order -> deterministic
    if (is_last && tid == 0) {
        __threadfence();
        float s = 0.0f;
        #pragma unroll
        for (int i = 0; i < NB; i++)
            s += ((volatile float*)g_partials)[i];
        out[0] = s;
        g_ticket = 0;                          // restore invariant for next replay
    }
}

extern "C" void kernel_launch(void* const* d_in, const int* in_sizes, int n_in,
                              void* d_out, int out_size)
{
    const float* pred  = (const float*)d_in[0];
    const float* label = (const float*)d_in[1];
    float* out = (float*)d_out;
    yolo_loss_kernel<<<NB, NT>>>(pred, label, out);
}